// round 11
// baseline (speedup 1.0000x reference)
#include <cuda_runtime.h>
#include <math.h>

// Shapes fixed by the problem:
//   hidden_states (8, 4096, 1024) f32, W (1024,1024) f32, b (1024) f32,
//   alpha (1) f32.  Output (8, 1, 1024) f32.
#define BATCH 8
#define SEQ   4096
#define HID   1024
#define NTHREADS 256              // 8 warps

// Bit layout (identical for x and W — consistency is all that matters):
//   chunk c, word k (0..3), bit `lane`  <->  element h = c*128 + 4*lane + k

// Scratch (__device__ globals; allocation-free rule). Rewritten every call.
__device__ uint4 g_xneg[BATCH][8];   // [batch][chunk] 4 sign words
__device__ uint4 g_xnz [BATCH][8];   // [batch][chunk] 4 nonzero words
__device__ float g_wpart[HID];       // per-row sum |W[o,:]|

// ---------------------------------------------------------------------------
// K1: grid = 1024 + 8.
//   blocks 0..1023 : row r -> g_wpart[r] = sum |W[r,:]|   (one float4/thread)
//   blocks 1024..1031 : pack x sign/nonzero bits for batch (blockIdx-1024)
// ---------------------------------------------------------------------------
__global__ void __launch_bounds__(NTHREADS)
prep_kernel(const float* __restrict__ x, const float* __restrict__ Wm)
{
    const int tid  = threadIdx.x;
    const int warp = tid >> 5;
    const int lane = tid & 31;

    if (blockIdx.x < HID) {
        // ---- |W| row sum ----
        const int row = blockIdx.x;
        const float4 wv = __ldg((const float4*)(Wm + (size_t)row * HID) + tid);
        float asum = fabsf(wv.x) + fabsf(wv.y) + fabsf(wv.z) + fabsf(wv.w);

        #pragma unroll
        for (int off = 16; off > 0; off >>= 1)
            asum += __shfl_xor_sync(0xffffffffu, asum, off);

        __shared__ float s_asum[8];
        if (lane == 0) s_asum[warp] = asum;
        __syncthreads();
        if (tid == 0) {
            float t = 0.0f;
            #pragma unroll
            for (int w2 = 0; w2 < 8; ++w2) t += s_asum[w2];
            g_wpart[row] = t;
        }
    } else {
        // ---- pack x bits for batch b ----
        const int b = blockIdx.x - HID;
        float4 v = __ldg((const float4*)(x + (size_t)b * SEQ * HID) + warp * 32 + lane);
        const float e[4] = {v.x, v.y, v.z, v.w};

        unsigned neg[4], nz[4];
        #pragma unroll
        for (int k = 0; k < 4; ++k) {
            neg[k] = __ballot_sync(0xffffffffu, e[k] < 0.0f);
            nz [k] = __ballot_sync(0xffffffffu, e[k] != 0.0f);
        }
        if (lane == 0) {
            g_xneg[b][warp] = make_uint4(neg[0], neg[1], neg[2], neg[3]);
            g_xnz [b][warp] = make_uint4(nz [0], nz [1], nz [2], nz [3]);
        }
    }
}

// ---------------------------------------------------------------------------
// K2: one block per W row. Warp w = chunk w (one float4 of W per thread),
// batch-in-lane popcount dot; block also reduces g_wpart -> wsum (L2-hot),
// then threads 0..7 write the row's 8 tanh outputs. No grid sync anywhere.
// ---------------------------------------------------------------------------
__global__ void __launch_bounds__(NTHREADS)
row_kernel(const float* __restrict__ Wm,
           const float* __restrict__ bias,
           const float* __restrict__ alpha,
           float* __restrict__ out)
{
    const int tid  = threadIdx.x;
    const int warp = tid >> 5;           // chunk
    const int lane = tid & 31;
    const int row  = blockIdx.x;
    const int mybatch = lane & 7;        // batch-in-lane

    // Issue all loads early: W (DRAM), packed x bits + wpart (L2)
    const float4 wv = __ldg((const float4*)(Wm + (size_t)row * HID) + warp * 32 + lane);
    const uint4 xn = g_xneg[mybatch][warp];
    const uint4 xz = g_xnz [mybatch][warp];
    const float4 wp = *((const float4*)g_wpart + tid);   // 256 thr x 4 = 1024

    // popcount dot
    const float we[4] = {wv.x, wv.y, wv.z, wv.w};
    const unsigned xnega[4] = {xn.x, xn.y, xn.z, xn.w};
    const unsigned xnza [4] = {xz.x, xz.y, xz.z, xz.w};

    int acc = 0;
    #pragma unroll
    for (int k = 0; k < 4; ++k) {
        unsigned wneg = __ballot_sync(0xffffffffu, we[k] < 0.0f);
        unsigned wnz  = __ballot_sync(0xffffffffu, we[k] != 0.0f);
        unsigned valid = xnza[k] & wnz;
        unsigned diff  = (xnega[k] ^ wneg) & valid;
        acc += __popc(valid) - 2 * __popc(diff);
    }

    // wsum partial: warp reduce
    float ws = wp.x + wp.y + wp.z + wp.w;
    #pragma unroll
    for (int off = 16; off > 0; off >>= 1)
        ws += __shfl_xor_sync(0xffffffffu, ws, off);

    __shared__ int   s_acc[8][BATCH];    // [warp][batch]
    __shared__ float s_ws[8];
    if (lane < BATCH) s_acc[warp][lane] = acc;    // lanes 0-7 carry batches 0-7
    if (lane == 0)    s_ws[warp] = ws;
    __syncthreads();

    if (tid < BATCH) {
        const int b = tid;
        int dot = 0;
        float wsum = 0.0f;
        #pragma unroll
        for (int w2 = 0; w2 < 8; ++w2) { dot += s_acc[w2][b]; wsum += s_ws[w2]; }

        const float wscale = wsum * (1.0f / ((float)HID * (float)HID));
        const float a      = fmaxf(__ldg(alpha), 1e-5f);
        const float scale  = a * wscale;
        out[b * HID + row] = tanhf(scale * (float)dot + __ldg(bias + row));
    }
}

extern "C" void kernel_launch(void* const* d_in, const int* in_sizes, int n_in,
                              void* d_out, int out_size)
{
    const float* x     = (const float*)d_in[0];
    const float* Wm    = (const float*)d_in[1];
    const float* bias  = (const float*)d_in[2];
    const float* alpha = (const float*)d_in[3];
    float* out = (float*)d_out;

    prep_kernel<<<HID + BATCH, NTHREADS>>>(x, Wm);
    row_kernel <<<HID, NTHREADS>>>(Wm, bias, alpha, out);
}